// round 14
// baseline (speedup 1.0000x reference)
#include <cuda_runtime.h>

#define B_ 128
#define T_ 1024
#define I_ 128
#define H_ 256
#define O_ 64

// Scratch (device globals — no allocations allowed)
__device__ float g_xw[(size_t)B_ * T_ * H_];  // 128 MB: x @ W_xh^T + b_h
__device__ float g_hs[(size_t)B_ * T_ * H_];  // 128 MB: hidden states

// ---------------------------------------------------------------------------
// Packed f32x2 helpers (sm_103a FFMA2 path)
// ---------------------------------------------------------------------------
__device__ __forceinline__ void ffma2(unsigned long long &acc,
                                      unsigned long long a,
                                      unsigned long long b) {
    asm("fma.rn.f32x2 %0, %1, %2, %0;" : "+l"(acc) : "l"(a), "l"(b));
}
__device__ __forceinline__ unsigned long long dup2(float a) {
    unsigned long long r;
    asm("mov.b64 %0, {%1, %1};" : "=l"(r) : "f"(a));
    return r;
}
__device__ __forceinline__ float2 unpack2(unsigned long long v) {
    float2 r;
    asm("mov.b64 {%0, %1}, %2;" : "=f"(r.x), "=f"(r.y) : "l"(v));
    return r;
}
__device__ __forceinline__ void cp_async16(unsigned smem_addr, const void* gptr) {
    asm volatile("cp.async.ca.shared.global [%0], [%1], 16;"
                 :: "r"(smem_addr), "l"(gptr));
}
#define CP_COMMIT() asm volatile("cp.async.commit_group;")
#define CP_WAIT(N)  asm volatile("cp.async.wait_group %0;" :: "n"(N))

// ---------------------------------------------------------------------------
// Phase 1: g_xw[row,h] = sum_i x[row,i] * W_xh[h,i] + b_h[h]
// NT GEMM: M=131072 rows, N=256, K=128. Tile 128x128. B (W_xh) transposed
// into smem up-front; A (x) streamed in 4 k-chunks of 32 via a 2-deep
// cp.async double buffer so loads overlap compute. 1 CTA/SM, 256 threads.
// ---------------------------------------------------------------------------
#define P1_APAD 36   // 32 k-floats + 4 pad
#define P1_BPAD 132
#define P1_KC 32
#define P1_NCH 4
#define P1_SMEM ((2 * 128 * P1_APAD + 128 * P1_BPAD) * 4)

__global__ __launch_bounds__(256, 1) void p1_kernel(
    const float* __restrict__ x, const float* __restrict__ Wxh,
    const float* __restrict__ bh) {
    extern __shared__ float sm[];
    float* As0 = sm;                         // [128][P1_APAD]
    float* As1 = sm + 128 * P1_APAD;         // [128][P1_APAD]
    float* BsT = sm + 2 * 128 * P1_APAD;     // [128 k][P1_BPAD]
    const int tid = threadIdx.x;
    const int mt = blockIdx.x >> 1;
    const int nt = blockIdx.x & 1;
    const int tx = tid & 15, ty = tid >> 4;

    const float* Ag = x + (size_t)mt * 128 * I_;
    float* bufs[2] = {As0, As1};

    // async A-chunk loader: 128 rows x 32 floats = 1024 float4, 4 per thread
    auto loadA = [&](int kc, float* buf) {
#pragma unroll
        for (int i = 0; i < 4; i++) {
            int lin = tid + 256 * i;
            int r = lin >> 3, c4 = lin & 7;
            unsigned dst = (unsigned)__cvta_generic_to_shared(
                buf + r * P1_APAD + c4 * 4);
            cp_async16(dst, Ag + (size_t)r * I_ + kc * P1_KC + c4 * 4);
        }
        CP_COMMIT();
    };

    loadA(0, bufs[0]);   // group: A0

    // B tile transposed (LDG from L2-hot Wxh + STS): BsT[k][n] = Wxh[nt*128+n][k]
    {
        int n = tid & 127, kg = tid >> 7;
        const float4* Bg = (const float4*)(Wxh + (size_t)(nt * 128 + n) * I_ + kg * 64);
#pragma unroll
        for (int q = 0; q < 16; q++) {
            float4 v = Bg[q];
            int kb = kg * 64 + q * 4;
            BsT[(kb + 0) * P1_BPAD + n] = v.x;
            BsT[(kb + 1) * P1_BPAD + n] = v.y;
            BsT[(kb + 2) * P1_BPAD + n] = v.z;
            BsT[(kb + 3) * P1_BPAD + n] = v.w;
        }
    }

    loadA(1, bufs[1]);   // group: A1   (pending: A0, A1)

    __syncthreads();     // BsT stores visible
    CP_WAIT(1);          // A0 landed
    __syncthreads();

    unsigned long long acc[8][4];
#pragma unroll
    for (int u = 0; u < 8; u++)
#pragma unroll
        for (int v = 0; v < 4; v++) acc[u][v] = 0ull;

#pragma unroll 1
    for (int kc = 0; kc < P1_NCH; kc++) {
        const float* Ab = bufs[kc & 1];
#pragma unroll 2
        for (int k = 0; k < P1_KC; k++) {
            unsigned long long a2[8], b2[4];
#pragma unroll
            for (int u = 0; u < 8; u++)
                a2[u] = dup2(Ab[(ty + 16 * u) * P1_APAD + k]);
#pragma unroll
            for (int v = 0; v < 4; v++)
                b2[v] = *(const unsigned long long*)(
                    BsT + (kc * P1_KC + k) * P1_BPAD + 2 * tx + 32 * v);
#pragma unroll
            for (int u = 0; u < 8; u++)
#pragma unroll
                for (int v = 0; v < 4; v++) ffma2(acc[u][v], a2[u], b2[v]);
        }
        if (kc < P1_NCH - 1) {
            __syncthreads();                    // done reading buf kc&1
            if (kc + 2 < P1_NCH) {
                loadA(kc + 2, bufs[kc & 1]);    // refill freed buffer
                CP_WAIT(1);                     // chunk kc+1 landed
            } else {
                CP_WAIT(0);                     // last pending chunk landed
            }
            __syncthreads();
        }
    }

    float2 bias[4];
#pragma unroll
    for (int v = 0; v < 4; v++)
        bias[v] = *(const float2*)(bh + nt * 128 + 2 * tx + 32 * v);
#pragma unroll
    for (int u = 0; u < 8; u++) {
        size_t row = (size_t)mt * 128 + ty + 16 * u;
        float* op = g_xw + row * H_ + nt * 128;
#pragma unroll
        for (int v = 0; v < 4; v++) {
            float2 r = unpack2(acc[u][v]);
            r.x += bias[v].x;
            r.y += bias[v].y;
            *(float2*)(op + 2 * tx + 32 * v) = r;
        }
    }
}

// ---------------------------------------------------------------------------
// Phase 2: sequential scan (R11 version verbatim, ~930us). 1 CTA per batch,
// 256 threads. W row h: k-chunks 0..45 in regs (92 u64), 46..63 in smem as
// ulonglong2 [j2][h]. 4-deep h-prefetch ring, 2-deep W ring, 4 acc chains,
// 4-deep xW register FIFO.
// ---------------------------------------------------------------------------
#define NJR 92
#define NJS2 18
#define RNN_SMEM (NJS2 * H_ * 16 + 2 * H_ * 4)
#define XF 4

__global__ __launch_bounds__(256, 1) void rnn_kernel(
    const float* __restrict__ Whh) {
    extern __shared__ char smraw[];
    ulonglong2* Wsm2 = (ulonglong2*)smraw;          // [NJS2][H_]
    float* hb = (float*)(smraw + NJS2 * H_ * 16);   // [2][H_]
    const int h = threadIdx.x;
    const int b = blockIdx.x;

    const unsigned long long* wrow =
        (const unsigned long long*)(Whh + (size_t)h * H_);
    unsigned long long wreg[NJR];
#pragma unroll
    for (int j = 0; j < NJR; j++) wreg[j] = wrow[j];
#pragma unroll
    for (int j2 = 0; j2 < NJS2; j2++) {
        ulonglong2 wv;
        wv.x = wrow[NJR + 2 * j2];
        wv.y = wrow[NJR + 2 * j2 + 1];
        Wsm2[j2 * H_ + h] = wv;
    }
    hb[h] = 0.0f;
    hb[H_ + h] = 0.0f;

    const float* xwp = g_xw + (size_t)b * T_ * H_ + h;
    float* hsp = g_hs + (size_t)b * T_ * H_ + h;

    float xwf[XF];
#pragma unroll
    for (int i = 0; i < XF; i++)
        xwf[i] = __ldg(xwp + (size_t)i * H_);
    __syncthreads();

    int cur = 0;
#pragma unroll 1
    for (int t = 0; t < T_; t++) {
        const ulonglong2* h2 = (const ulonglong2*)(hb + cur * H_);
        unsigned long long acc0 = 0ull, acc1 = 0ull, acc2 = 0ull, acc3 = 0ull;

        ulonglong2 hring[4];
#pragma unroll
        for (int i = 0; i < 4; i++) hring[i] = h2[i];
        ulonglong2 wring[2];
        wring[0] = Wsm2[0 * H_ + h];
        wring[1] = Wsm2[1 * H_ + h];

#pragma unroll
        for (int j = 0; j < NJR / 2; j++) {
            ulonglong2 hv = hring[j & 3];
            hring[j & 3] = h2[j + 4];
            if (j & 1) {
                ffma2(acc2, hv.x, wreg[2 * j]);
                ffma2(acc3, hv.y, wreg[2 * j + 1]);
            } else {
                ffma2(acc0, hv.x, wreg[2 * j]);
                ffma2(acc1, hv.y, wreg[2 * j + 1]);
            }
        }
#pragma unroll
        for (int j2 = 0; j2 < NJS2; j2++) {
            const int j = NJR / 2 + j2;
            ulonglong2 hv = hring[j & 3];
            if (j + 4 < 64) hring[j & 3] = h2[j + 4];
            ulonglong2 wv = wring[j2 & 1];
            if (j2 + 2 < NJS2) wring[j2 & 1] = Wsm2[(j2 + 2) * H_ + h];
            if (j & 1) {
                ffma2(acc2, hv.x, wv.x);
                ffma2(acc3, hv.y, wv.y);
            } else {
                ffma2(acc0, hv.x, wv.x);
                ffma2(acc1, hv.y, wv.y);
            }
        }

        float2 a0 = unpack2(acc0), a1 = unpack2(acc1);
        float2 a2 = unpack2(acc2), a3 = unpack2(acc3);
        float s = ((a0.x + a0.y) + (a1.x + a1.y)) +
                  ((a2.x + a2.y) + (a3.x + a3.y));
        float hnew = fmaxf(xwf[t & (XF - 1)] + s, 0.0f);
        hb[(cur ^ 1) * H_ + h] = hnew;
        hsp[(size_t)t * H_] = hnew;
        xwf[t & (XF - 1)] = __ldg(xwp + (size_t)((t + XF) & (T_ - 1)) * H_);
        cur ^= 1;
        __syncthreads();
    }
}

// ---------------------------------------------------------------------------
// Phase 3: out[row,o] = sum_h g_hs[row,h] * W_out[o,h] + b_out[o]
// M=131072, N=64, K=256. Tile 128 rows x 64 cols. (R4 version, ~90us)
// ---------------------------------------------------------------------------
#define P3_WPAD 66
#define P3_APAD 68
#define P3_SMEM ((256 * P3_WPAD + 128 * P3_APAD) * 4)

__global__ __launch_bounds__(256, 1) void p3_kernel(
    const float* __restrict__ Wout, const float* __restrict__ bout,
    float* __restrict__ out) {
    extern __shared__ float sm[];
    float* WsT = sm;                    // [256 k][P3_WPAD] (k x o)
    float* As  = sm + 256 * P3_WPAD;    // [128 m][P3_APAD] (m x k-chunk)
    const int tid = threadIdx.x;
    const int mt = blockIdx.x;

    {
        int o = tid >> 2, kq = tid & 3;
        const float4* Wg = (const float4*)(Wout + (size_t)o * H_ + kq * 64);
#pragma unroll
        for (int q = 0; q < 16; q++) {
            float4 v = Wg[q];
            int kb = kq * 64 + q * 4;
            WsT[(kb + 0) * P3_WPAD + o] = v.x;
            WsT[(kb + 1) * P3_WPAD + o] = v.y;
            WsT[(kb + 2) * P3_WPAD + o] = v.z;
            WsT[(kb + 3) * P3_WPAD + o] = v.w;
        }
    }

    const int tx = tid & 15, ty = tid >> 4;
    unsigned long long acc[8][2];
#pragma unroll
    for (int u = 0; u < 8; u++) { acc[u][0] = 0ull; acc[u][1] = 0ull; }

    for (int kc = 0; kc < 4; kc++) {
        __syncthreads();
#pragma unroll
        for (int i = 0; i < 8; i++) {
            int lin = tid + 256 * i;
            int r = lin >> 4, c4 = lin & 15;
            float4 v = *(const float4*)(g_hs + ((size_t)mt * 128 + r) * H_ +
                                        kc * 64 + c4 * 4);
            *(float4*)(As + r * P3_APAD + c4 * 4) = v;
        }
        __syncthreads();
#pragma unroll 4
        for (int k = 0; k < 64; k++) {
            unsigned long long b0 = *(const unsigned long long*)(
                WsT + (kc * 64 + k) * P3_WPAD + 2 * tx);
            unsigned long long b1 = *(const unsigned long long*)(
                WsT + (kc * 64 + k) * P3_WPAD + 2 * tx + 32);
#pragma unroll
            for (int u = 0; u < 8; u++) {
                unsigned long long a2 = dup2(As[(ty + 16 * u) * P3_APAD + k]);
                ffma2(acc[u][0], a2, b0);
                ffma2(acc[u][1], a2, b1);
            }
        }
    }

    float2 bias0 = *(const float2*)(bout + 2 * tx);
    float2 bias1 = *(const float2*)(bout + 2 * tx + 32);
#pragma unroll
    for (int u = 0; u < 8; u++) {
        size_t row = (size_t)mt * 128 + ty + 16 * u;
        float2 r0 = unpack2(acc[u][0]);
        float2 r1 = unpack2(acc[u][1]);
        r0.x += bias0.x; r0.y += bias0.y;
        r1.x += bias1.x; r1.y += bias1.y;
        *(float2*)(out + row * O_ + 2 * tx) = r0;
        *(float2*)(out + row * O_ + 2 * tx + 32) = r1;
    }
}

// ---------------------------------------------------------------------------
extern "C" void kernel_launch(void* const* d_in, const int* in_sizes, int n_in,
                              void* d_out, int out_size) {
    const float* x    = (const float*)d_in[0];
    const float* Wxh  = (const float*)d_in[1];
    const float* Whh  = (const float*)d_in[2];
    const float* bh   = (const float*)d_in[3];
    const float* Wout = (const float*)d_in[4];
    const float* bout = (const float*)d_in[5];
    float* out = (float*)d_out;

    cudaFuncSetAttribute(p1_kernel, cudaFuncAttributeMaxDynamicSharedMemorySize, P1_SMEM);
    cudaFuncSetAttribute(rnn_kernel, cudaFuncAttributeMaxDynamicSharedMemorySize, RNN_SMEM);
    cudaFuncSetAttribute(p3_kernel, cudaFuncAttributeMaxDynamicSharedMemorySize, P3_SMEM);

    p1_kernel<<<(B_ * T_ / 128) * 2, 256, P1_SMEM>>>(x, Wxh, bh);
    rnn_kernel<<<B_, 256, RNN_SMEM>>>(Whh);
    p3_kernel<<<B_ * T_ / 128, 256, P3_SMEM>>>(Wout, bout, out);
}

// round 15
// speedup vs baseline: 1.0047x; 1.0047x over previous
#include <cuda_runtime.h>

#define B_ 128
#define T_ 1024
#define I_ 128
#define H_ 256
#define O_ 64

// Scratch (device globals — no allocations allowed)
__device__ float g_xw[(size_t)B_ * T_ * H_];  // 128 MB: x @ W_xh^T + b_h
__device__ float g_hs[(size_t)B_ * T_ * H_];  // 128 MB: hidden states

// ---------------------------------------------------------------------------
// Packed f32x2 helpers (sm_103a FFMA2 path)
// ---------------------------------------------------------------------------
__device__ __forceinline__ void ffma2(unsigned long long &acc,
                                      unsigned long long a,
                                      unsigned long long b) {
    asm("fma.rn.f32x2 %0, %1, %2, %0;" : "+l"(acc) : "l"(a), "l"(b));
}
__device__ __forceinline__ unsigned long long dup2(float a) {
    unsigned long long r;
    asm("mov.b64 %0, {%1, %1};" : "=l"(r) : "f"(a));
    return r;
}
__device__ __forceinline__ float2 unpack2(unsigned long long v) {
    float2 r;
    asm("mov.b64 {%0, %1}, %2;" : "=f"(r.x), "=f"(r.y) : "l"(v));
    return r;
}

// ---------------------------------------------------------------------------
// Phase 1: g_xw[row,h] = sum_i x[row,i] * W_xh[h,i] + b_h[h]
// NT GEMM: M=131072 rows, N=256, K=128. Tile 128 m x 256 n (full N),
// 512 threads (16 warps, 4/SMSP for latency hiding), 1 CTA/SM.
// Per thread: 4 m x 16 n (32 u64 acc, ~100 regs -> no cap, no spill).
// K in 2 chunks of 64 -> smem 101KB.
// ---------------------------------------------------------------------------
#define P1_APAD 68   // 64 k-floats + 4 pad
#define P1_BPAD 260  // 256 n + 4 pad
#define P1_SMEM ((128 * P1_APAD + 64 * P1_BPAD) * 4)

__global__ __launch_bounds__(512, 1) void p1_kernel(
    const float* __restrict__ x, const float* __restrict__ Wxh,
    const float* __restrict__ bh) {
    extern __shared__ float sm[];
    float* As  = sm;                  // [128 m][P1_APAD]  (m x k-chunk)
    float* BsT = sm + 128 * P1_APAD;  // [64 k][P1_BPAD]   (k x n)
    const int tid = threadIdx.x;
    const int mt = blockIdx.x;
    const int tx = tid & 15;          // 16 n-groups: cols 4tx + 64g
    const int ty = tid >> 4;          // 32 m-groups: rows 4ty + r

    unsigned long long acc[4][8];
#pragma unroll
    for (int r = 0; r < 4; r++)
#pragma unroll
        for (int v = 0; v < 8; v++) acc[r][v] = 0ull;

    const int lm = tid >> 2, lkq = tid & 3;   // A-loader: row, k-quad
    const int ln = tid & 255, lkg = tid >> 8; // B-loader: col n, k-group

    for (int kc = 0; kc < 2; kc++) {
        if (kc) __syncthreads();
        // A chunk: 128 rows x 64 k
        {
            const float4* Ag = (const float4*)(x + (size_t)(mt * 128 + lm) * I_ +
                                               kc * 64);
#pragma unroll
            for (int q = 0; q < 4; q++) {
                float4 v = Ag[lkq * 4 + q];
                *(float4*)(As + lm * P1_APAD + (lkq * 4 + q) * 4) = v;
            }
        }
        // B chunk transposed: BsT[k][n] = Wxh[n][kc*64 + k]
        {
            const float4* Bg = (const float4*)(Wxh + (size_t)ln * I_ +
                                               kc * 64 + lkg * 32);
#pragma unroll
            for (int q = 0; q < 8; q++) {
                float4 v = Bg[q];
                int kb = lkg * 32 + q * 4;
                BsT[(kb + 0) * P1_BPAD + ln] = v.x;
                BsT[(kb + 1) * P1_BPAD + ln] = v.y;
                BsT[(kb + 2) * P1_BPAD + ln] = v.z;
                BsT[(kb + 3) * P1_BPAD + ln] = v.w;
            }
        }
        __syncthreads();

#pragma unroll 2
        for (int k = 0; k < 64; k++) {
            unsigned long long a2[4];
            ulonglong2 bb[4];
#pragma unroll
            for (int r = 0; r < 4; r++)
                a2[r] = dup2(As[(4 * ty + r) * P1_APAD + k]);
#pragma unroll
            for (int g = 0; g < 4; g++)
                bb[g] = *(const ulonglong2*)(BsT + k * P1_BPAD + 4 * tx + 64 * g);
#pragma unroll
            for (int r = 0; r < 4; r++)
#pragma unroll
                for (int g = 0; g < 4; g++) {
                    ffma2(acc[r][2 * g],     a2[r], bb[g].x);
                    ffma2(acc[r][2 * g + 1], a2[r], bb[g].y);
                }
        }
    }

    float4 bias[4];
#pragma unroll
    for (int g = 0; g < 4; g++)
        bias[g] = *(const float4*)(bh + 4 * tx + 64 * g);
#pragma unroll
    for (int r = 0; r < 4; r++) {
        size_t row = (size_t)mt * 128 + 4 * ty + r;
        float* op = g_xw + row * H_;
#pragma unroll
        for (int g = 0; g < 4; g++) {
            float2 r0 = unpack2(acc[r][2 * g]);
            float2 r1 = unpack2(acc[r][2 * g + 1]);
            float4 o;
            o.x = r0.x + bias[g].x;
            o.y = r0.y + bias[g].y;
            o.z = r1.x + bias[g].z;
            o.w = r1.y + bias[g].w;
            *(float4*)(op + 4 * tx + 64 * g) = o;
        }
    }
}

// ---------------------------------------------------------------------------
// Phase 2: sequential scan (R11 version verbatim, ~930us). 1 CTA per batch,
// 256 threads. W row h: k-chunks 0..45 in regs (92 u64), 46..63 in smem as
// ulonglong2 [j2][h]. 4-deep h-prefetch ring, 2-deep W ring, 4 acc chains,
// 4-deep xW register FIFO.
// ---------------------------------------------------------------------------
#define NJR 92
#define NJS2 18
#define RNN_SMEM (NJS2 * H_ * 16 + 2 * H_ * 4)
#define XF 4

__global__ __launch_bounds__(256, 1) void rnn_kernel(
    const float* __restrict__ Whh) {
    extern __shared__ char smraw[];
    ulonglong2* Wsm2 = (ulonglong2*)smraw;          // [NJS2][H_]
    float* hb = (float*)(smraw + NJS2 * H_ * 16);   // [2][H_]
    const int h = threadIdx.x;
    const int b = blockIdx.x;

    const unsigned long long* wrow =
        (const unsigned long long*)(Whh + (size_t)h * H_);
    unsigned long long wreg[NJR];
#pragma unroll
    for (int j = 0; j < NJR; j++) wreg[j] = wrow[j];
#pragma unroll
    for (int j2 = 0; j2 < NJS2; j2++) {
        ulonglong2 wv;
        wv.x = wrow[NJR + 2 * j2];
        wv.y = wrow[NJR + 2 * j2 + 1];
        Wsm2[j2 * H_ + h] = wv;
    }
    hb[h] = 0.0f;
    hb[H_ + h] = 0.0f;

    const float* xwp = g_xw + (size_t)b * T_ * H_ + h;
    float* hsp = g_hs + (size_t)b * T_ * H_ + h;

    float xwf[XF];
#pragma unroll
    for (int i = 0; i < XF; i++)
        xwf[i] = __ldg(xwp + (size_t)i * H_);
    __syncthreads();

    int cur = 0;
#pragma unroll 1
    for (int t = 0; t < T_; t++) {
        const ulonglong2* h2 = (const ulonglong2*)(hb + cur * H_);
        unsigned long long acc0 = 0ull, acc1 = 0ull, acc2 = 0ull, acc3 = 0ull;

        ulonglong2 hring[4];
#pragma unroll
        for (int i = 0; i < 4; i++) hring[i] = h2[i];
        ulonglong2 wring[2];
        wring[0] = Wsm2[0 * H_ + h];
        wring[1] = Wsm2[1 * H_ + h];

#pragma unroll
        for (int j = 0; j < NJR / 2; j++) {
            ulonglong2 hv = hring[j & 3];
            hring[j & 3] = h2[j + 4];
            if (j & 1) {
                ffma2(acc2, hv.x, wreg[2 * j]);
                ffma2(acc3, hv.y, wreg[2 * j + 1]);
            } else {
                ffma2(acc0, hv.x, wreg[2 * j]);
                ffma2(acc1, hv.y, wreg[2 * j + 1]);
            }
        }
#pragma unroll
        for (int j2 = 0; j2 < NJS2; j2++) {
            const int j = NJR / 2 + j2;
            ulonglong2 hv = hring[j & 3];
            if (j + 4 < 64) hring[j & 3] = h2[j + 4];
            ulonglong2 wv = wring[j2 & 1];
            if (j2 + 2 < NJS2) wring[j2 & 1] = Wsm2[(j2 + 2) * H_ + h];
            if (j & 1) {
                ffma2(acc2, hv.x, wv.x);
                ffma2(acc3, hv.y, wv.y);
            } else {
                ffma2(acc0, hv.x, wv.x);
                ffma2(acc1, hv.y, wv.y);
            }
        }

        float2 a0 = unpack2(acc0), a1 = unpack2(acc1);
        float2 a2 = unpack2(acc2), a3 = unpack2(acc3);
        float s = ((a0.x + a0.y) + (a1.x + a1.y)) +
                  ((a2.x + a2.y) + (a3.x + a3.y));
        float hnew = fmaxf(xwf[t & (XF - 1)] + s, 0.0f);
        hb[(cur ^ 1) * H_ + h] = hnew;
        hsp[(size_t)t * H_] = hnew;
        xwf[t & (XF - 1)] = __ldg(xwp + (size_t)((t + XF) & (T_ - 1)) * H_);
        cur ^= 1;
        __syncthreads();
    }
}

// ---------------------------------------------------------------------------
// Phase 3: out[row,o] = sum_h g_hs[row,h] * W_out[o,h] + b_out[o]
// M=131072, N=64, K=256. Tile 128 rows x 64 cols. (R4 version, ~90us)
// ---------------------------------------------------------------------------
#define P3_WPAD 66
#define P3_APAD 68
#define P3_SMEM ((256 * P3_WPAD + 128 * P3_APAD) * 4)

__global__ __launch_bounds__(256, 1) void p3_kernel(
    const float* __restrict__ Wout, const float* __restrict__ bout,
    float* __restrict__ out) {
    extern __shared__ float sm[];
    float* WsT = sm;                    // [256 k][P3_WPAD] (k x o)
    float* As  = sm + 256 * P3_WPAD;    // [128 m][P3_APAD] (m x k-chunk)
    const int tid = threadIdx.x;
    const int mt = blockIdx.x;

    {
        int o = tid >> 2, kq = tid & 3;
        const float4* Wg = (const float4*)(Wout + (size_t)o * H_ + kq * 64);
#pragma unroll
        for (int q = 0; q < 16; q++) {
            float4 v = Wg[q];
            int kb = kq * 64 + q * 4;
            WsT[(kb + 0) * P3_WPAD + o] = v.x;
            WsT[(kb + 1) * P3_WPAD + o] = v.y;
            WsT[(kb + 2) * P3_WPAD + o] = v.z;
            WsT[(kb + 3) * P3_WPAD + o] = v.w;
        }
    }

    const int tx = tid & 15, ty = tid >> 4;
    unsigned long long acc[8][2];
#pragma unroll
    for (int u = 0; u < 8; u++) { acc[u][0] = 0ull; acc[u][1] = 0ull; }

    for (int kc = 0; kc < 4; kc++) {
        __syncthreads();
#pragma unroll
        for (int i = 0; i < 8; i++) {
            int lin = tid + 256 * i;
            int r = lin >> 4, c4 = lin & 15;
            float4 v = *(const float4*)(g_hs + ((size_t)mt * 128 + r) * H_ +
                                        kc * 64 + c4 * 4);
            *(float4*)(As + r * P3_APAD + c4 * 4) = v;
        }
        __syncthreads();
#pragma unroll 4
        for (int k = 0; k < 64; k++) {
            unsigned long long b0 = *(const unsigned long long*)(
                WsT + (kc * 64 + k) * P3_WPAD + 2 * tx);
            unsigned long long b1 = *(const unsigned long long*)(
                WsT + (kc * 64 + k) * P3_WPAD + 2 * tx + 32);
#pragma unroll
            for (int u = 0; u < 8; u++) {
                unsigned long long a2 = dup2(As[(ty + 16 * u) * P3_APAD + k]);
                ffma2(acc[u][0], a2, b0);
                ffma2(acc[u][1], a2, b1);
            }
        }
    }

    float2 bias0 = *(const float2*)(bout + 2 * tx);
    float2 bias1 = *(const float2*)(bout + 2 * tx + 32);
#pragma unroll
    for (int u = 0; u < 8; u++) {
        size_t row = (size_t)mt * 128 + ty + 16 * u;
        float2 r0 = unpack2(acc[u][0]);
        float2 r1 = unpack2(acc[u][1]);
        r0.x += bias0.x; r0.y += bias0.y;
        r1.x += bias1.x; r1.y += bias1.y;
        *(float2*)(out + row * O_ + 2 * tx) = r0;
        *(float2*)(out + row * O_ + 2 * tx + 32) = r1;
    }
}

// ---------------------------------------------------------------------------
extern "C" void kernel_launch(void* const* d_in, const int* in_sizes, int n_in,
                              void* d_out, int out_size) {
    const float* x    = (const float*)d_in[0];
    const float* Wxh  = (const float*)d_in[1];
    const float* Whh  = (const float*)d_in[2];
    const float* bh   = (const float*)d_in[3];
    const float* Wout = (const float*)d_in[4];
    const float* bout = (const float*)d_in[5];
    float* out = (float*)d_out;

    cudaFuncSetAttribute(p1_kernel, cudaFuncAttributeMaxDynamicSharedMemorySize, P1_SMEM);
    cudaFuncSetAttribute(rnn_kernel, cudaFuncAttributeMaxDynamicSharedMemorySize, RNN_SMEM);
    cudaFuncSetAttribute(p3_kernel, cudaFuncAttributeMaxDynamicSharedMemorySize, P3_SMEM);

    p1_kernel<<<B_ * T_ / 128, 512, P1_SMEM>>>(x, Wxh, bh);
    rnn_kernel<<<B_, 256, RNN_SMEM>>>(Whh);
    p3_kernel<<<B_ * T_ / 128, 256, P3_SMEM>>>(Wout, bout, out);
}